// round 6
// baseline (speedup 1.0000x reference)
#include <cuda_runtime.h>
#include <cuda_bf16.h>

// ConvSpatialPropagationNet_71949292143069
//
// Math (verified on HW in R1, rel_err 6.1e-8): the reference's propagation
// multiplies the padded gate tensor by the padded depth ELEMENTWISE (no
// neighbor gather), so each step is d <- (1-G)*raw + G*d with d0 = raw,
// whose fixed point is d = raw = blur_depth. Output = copy of d_in[1].
//
// Round history (SM copy kernels — DRAM% invariant at ~25%, latency/ramp floor):
//   R1: 3344 CTAs, MLP=1 -> 6.66 us   (best SM variant)
//   R4:  836 CTAs, MLP=4 -> 7.23 us
//   R5: 1672 CTAs, MLP=2 -> 8.42 us
// Conclusion: a ~7 us floor independent of SM-side tuning. R6 switches the
// mechanism: graph-captured cudaMemcpyAsync D2D (explicitly allowed by the
// harness), which becomes a memcpy node executed by the copy engine — no
// CTA launch/ramp across 148 SMs, immediate full-width bursts.

extern "C" void kernel_launch(void* const* d_in, const int* in_sizes, int n_in,
                              void* d_out, int out_size) {
    // Inputs (metadata order): guidance, blur_depth, sparse_depth, sum_w
    const float* blur_depth = (const float*)d_in[1];

    size_t bytes = (size_t)in_sizes[1] * sizeof(float);   // 13,697,024 B

    cudaMemcpyAsync(d_out, blur_depth, bytes, cudaMemcpyDeviceToDevice);
}